// round 4
// baseline (speedup 1.0000x reference)
#include <cuda_runtime.h>
#include <math_constants.h>

#define NX 1000

// ---------------- device-global scratch (zero-init is the neutral state) ----
__device__ unsigned int g_negmin_bits;   // holds max(~enc(v))  -> min value
__device__ unsigned int g_max_bits;      // holds max( enc(v))  -> max value
__device__ unsigned int g_hist[2][NX];

__device__ __forceinline__ unsigned int enc_f(float f) {
    unsigned int u = __float_as_uint(f);
    return (u & 0x80000000u) ? ~u : (u | 0x80000000u);
}
__device__ __forceinline__ float dec_f(unsigned int u) {
    u = (u & 0x80000000u) ? (u & 0x7FFFFFFFu) : ~u;
    return __uint_as_float(u);
}

// The linspace grid point, matching f32 "lo + j*step" with exact endpoint.
__device__ __forceinline__ float xval(int j, float lo, float hi, float step) {
    return (j >= NX - 1) ? hi : fmaf((float)j, step, lo);
}

__device__ __forceinline__ void mm8(float4 v, float4 w, float& mn, float& mx) {
    mn = fminf(mn, fminf(fminf(v.x, v.y), fminf(v.z, v.w)));
    mx = fmaxf(mx, fmaxf(fmaxf(v.x, v.y), fmaxf(v.z, v.w)));
    mn = fminf(mn, fminf(fminf(w.x, w.y), fminf(w.z, w.w)));
    mx = fmaxf(mx, fmaxf(fmaxf(w.x, w.y), fmaxf(w.z, w.w)));
}

// ---------------- kernel 1: global min/max over both arrays -----------------
__global__ void __launch_bounds__(256) minmax_k(const float* __restrict__ a,
                                                const float* __restrict__ b, int n) {
    int n4 = n >> 2;
    const float4* __restrict__ a4 = (const float4*)a;
    const float4* __restrict__ b4 = (const float4*)b;
    float mn = CUDART_INF_F, mx = -CUDART_INF_F;
    int S = gridDim.x * blockDim.x;
    int i = blockIdx.x * blockDim.x + threadIdx.x;
    // 4-way unroll: 8 independent LDG.128 in flight
    for (; i + 3 * S < n4; i += 4 * S) {
        float4 v0 = a4[i];
        float4 v1 = a4[i + S];
        float4 v2 = a4[i + 2 * S];
        float4 v3 = a4[i + 3 * S];
        float4 w0 = b4[i];
        float4 w1 = b4[i + S];
        float4 w2 = b4[i + 2 * S];
        float4 w3 = b4[i + 3 * S];
        mm8(v0, w0, mn, mx);
        mm8(v1, w1, mn, mx);
        mm8(v2, w2, mn, mx);
        mm8(v3, w3, mn, mx);
    }
    for (; i < n4; i += S) {
        float4 v0 = a4[i];
        float4 w0 = b4[i];
        mm8(v0, w0, mn, mx);
    }
    if (blockIdx.x == 0 && threadIdx.x == 0) {   // scalar tail (n % 4)
        for (int k = (n4 << 2); k < n; ++k) {
            mn = fminf(mn, fminf(a[k], b[k]));
            mx = fmaxf(mx, fmaxf(a[k], b[k]));
        }
    }
    for (int o = 16; o; o >>= 1) {
        mn = fminf(mn, __shfl_xor_sync(0xFFFFFFFFu, mn, o));
        mx = fmaxf(mx, __shfl_xor_sync(0xFFFFFFFFu, mx, o));
    }
    __shared__ float smn[32], smx[32];
    int lane = threadIdx.x & 31, w = threadIdx.x >> 5;
    if (lane == 0) { smn[w] = mn; smx[w] = mx; }
    __syncthreads();
    if (threadIdx.x < 32) {
        int nw = blockDim.x >> 5;
        mn = (threadIdx.x < nw) ? smn[threadIdx.x] : CUDART_INF_F;
        mx = (threadIdx.x < nw) ? smx[threadIdx.x] : -CUDART_INF_F;
        for (int o = 16; o; o >>= 1) {
            mn = fminf(mn, __shfl_xor_sync(0xFFFFFFFFu, mn, o));
            mx = fmaxf(mx, __shfl_xor_sync(0xFFFFFFFFu, mx, o));
        }
        if (threadIdx.x == 0) {
            atomicMax(&g_negmin_bits, ~enc_f(mn));
            atomicMax(&g_max_bits, enc_f(mx));
        }
    }
}

// first grid index j with x_j >= v — branchless (fixup needs at most 2 steps)
__device__ __forceinline__ int binof(float v, float lo, float hi,
                                     float step, float invstep) {
    float f = (v - lo) * invstep;
    int j = (int)ceilf(f);
    j = max(0, min(j, NX - 1));
    j += (j < NX - 1 && xval(j, lo, hi, step) < v) ? 1 : 0;
    j += (j < NX - 1 && xval(j, lo, hi, step) < v) ? 1 : 0;
    j -= (j > 0 && xval(j - 1, lo, hi, step) >= v) ? 1 : 0;
    j -= (j > 0 && xval(j - 1, lo, hi, step) >= v) ? 1 : 0;
    return j;
}

__device__ __forceinline__ void hist8(float4 v, float4 w,
                                      unsigned int* h0, unsigned int* h1,
                                      float lo, float hi, float step, float invstep) {
    atomicAdd(&h0[binof(v.x, lo, hi, step, invstep)], 1u);
    atomicAdd(&h0[binof(v.y, lo, hi, step, invstep)], 1u);
    atomicAdd(&h0[binof(v.z, lo, hi, step, invstep)], 1u);
    atomicAdd(&h0[binof(v.w, lo, hi, step, invstep)], 1u);
    atomicAdd(&h1[binof(w.x, lo, hi, step, invstep)], 1u);
    atomicAdd(&h1[binof(w.y, lo, hi, step, invstep)], 1u);
    atomicAdd(&h1[binof(w.z, lo, hi, step, invstep)], 1u);
    atomicAdd(&h1[binof(w.w, lo, hi, step, invstep)], 1u);
}

// ---------------- kernel 2: 2x 1000-bin histograms --------------------------
__global__ void __launch_bounds__(256) hist_k(const float* __restrict__ a,
                                              const float* __restrict__ b, int n) {
    __shared__ unsigned int sh[2][NX];
    for (int i = threadIdx.x; i < 2 * NX; i += blockDim.x)
        ((unsigned int*)sh)[i] = 0u;
    __syncthreads();

    float lo = dec_f(~g_negmin_bits);
    float hi = dec_f(g_max_bits);
    float step = (hi - lo) / (float)(NX - 1);
    float invstep = (step > 0.0f) ? (1.0f / step) : 0.0f;

    int n4 = n >> 2;
    const float4* __restrict__ a4 = (const float4*)a;
    const float4* __restrict__ b4 = (const float4*)b;
    int S = gridDim.x * blockDim.x;
    int i = blockIdx.x * blockDim.x + threadIdx.x;
    for (; i + 3 * S < n4; i += 4 * S) {
        float4 v0 = a4[i];
        float4 v1 = a4[i + S];
        float4 v2 = a4[i + 2 * S];
        float4 v3 = a4[i + 3 * S];
        float4 w0 = b4[i];
        float4 w1 = b4[i + S];
        float4 w2 = b4[i + 2 * S];
        float4 w3 = b4[i + 3 * S];
        hist8(v0, w0, sh[0], sh[1], lo, hi, step, invstep);
        hist8(v1, w1, sh[0], sh[1], lo, hi, step, invstep);
        hist8(v2, w2, sh[0], sh[1], lo, hi, step, invstep);
        hist8(v3, w3, sh[0], sh[1], lo, hi, step, invstep);
    }
    for (; i < n4; i += S) {
        float4 v0 = a4[i];
        float4 w0 = b4[i];
        hist8(v0, w0, sh[0], sh[1], lo, hi, step, invstep);
    }
    if (blockIdx.x == 0 && threadIdx.x == 0) {   // scalar tail
        for (int k = (n4 << 2); k < n; ++k) {
            atomicAdd(&sh[0][binof(a[k], lo, hi, step, invstep)], 1u);
            atomicAdd(&sh[1][binof(b[k], lo, hi, step, invstep)], 1u);
        }
    }
    __syncthreads();
    for (int i2 = threadIdx.x; i2 < NX; i2 += blockDim.x) {
        unsigned int c0 = sh[0][i2];
        unsigned int c1 = sh[1][i2];
        if (c0) atomicAdd(&g_hist[0][i2], c0);
        if (c1) atomicAdd(&g_hist[1][i2], c1);
    }
}

// ---------------- kernel 3: scan + trapz + STATE RESET (single block) -------
__global__ void finish_k(float* __restrict__ out, int n) {
    int t = threadIdx.x;
    int lane = t & 31, w = t >> 5;

    float lo = dec_f(~g_negmin_bits);
    float hi = dec_f(g_max_bits);
    float step = (hi - lo) / (float)(NX - 1);

    unsigned int s0 = (t < NX) ? g_hist[0][t] : 0u;
    unsigned int s1 = (t < NX) ? g_hist[1][t] : 0u;

    #pragma unroll
    for (int o = 1; o < 32; o <<= 1) {
        unsigned int u0 = __shfl_up_sync(0xFFFFFFFFu, s0, o);
        unsigned int u1 = __shfl_up_sync(0xFFFFFFFFu, s1, o);
        if (lane >= o) { s0 += u0; s1 += u1; }
    }
    __shared__ unsigned int ws0[32], ws1[32];
    if (lane == 31) { ws0[w] = s0; ws1[w] = s1; }
    __syncthreads();
    if (w == 0) {
        unsigned int a0 = ws0[lane], a1 = ws1[lane];
        #pragma unroll
        for (int o = 1; o < 32; o <<= 1) {
            unsigned int u0 = __shfl_up_sync(0xFFFFFFFFu, a0, o);
            unsigned int u1 = __shfl_up_sync(0xFFFFFFFFu, a1, o);
            if (lane >= o) { a0 += u0; a1 += u1; }
        }
        ws0[lane] = a0; ws1[lane] = a1;
    }
    __syncthreads();
    if (w > 0) { s0 += ws0[w - 1]; s1 += ws1[w - 1]; }

    __shared__ unsigned int sc0[1024], sc1[1024];
    sc0[t] = s0; sc1[t] = s1;
    __syncthreads();

    float nf = (float)n;
    double acc = 0.0;
    if (t < NX - 1) {
        float cp0 = (float)sc0[t] / nf;
        float ct0 = (float)sc1[t] / nf;
        float cp1 = (float)sc0[t + 1] / nf;
        float ct1 = (float)sc1[t + 1] / nf;
        float y0 = cp0 - ct0; y0 = y0 * y0;
        float y1 = cp1 - ct1; y1 = y1 * y1;
        float dx = xval(t + 1, lo, hi, step) - xval(t, lo, hi, step);
        acc = (double)(0.5f * (y0 + y1) * dx);
    }
    for (int o = 16; o; o >>= 1)
        acc += __shfl_xor_sync(0xFFFFFFFFu, acc, o);
    __shared__ double sd[32];
    if (lane == 0) sd[w] = acc;
    __syncthreads();
    if (t < 32) {
        acc = sd[t];
        for (int o = 16; o; o >>= 1)
            acc += __shfl_xor_sync(0xFFFFFFFFu, acc, o);
        if (t == 0) out[0] = (float)acc;
    }

    // ---- reset all device state for the next graph replay ----
    __syncthreads();
    for (int i = t; i < 2 * NX; i += 1024)
        ((unsigned int*)g_hist)[i] = 0u;
    if (t == 0) { g_negmin_bits = 0u; g_max_bits = 0u; }
}

// ---------------- launch ----------------------------------------------------
extern "C" void kernel_launch(void* const* d_in, const int* in_sizes, int n_in,
                              void* d_out, int out_size) {
    const float* p = (const float*)d_in[0];
    const float* tg = (const float*)d_in[1];
    int n = in_sizes[0];

    minmax_k<<<1184, 256>>>(p, tg, n);
    hist_k<<<1184, 256>>>(p, tg, n);
    finish_k<<<1, 1024>>>((float*)d_out, n);
}

// round 5
// speedup vs baseline: 2.0187x; 2.0187x over previous
#include <cuda_runtime.h>
#include <math_constants.h>

#define NX 1000

// ---------------- device-global scratch (zero-init is the neutral state) ----
__device__ unsigned int g_negmin_bits;   // holds max(~enc(v))  -> min value
__device__ unsigned int g_max_bits;      // holds max( enc(v))  -> max value
__device__ unsigned int g_hist[2][NX];

__device__ __forceinline__ unsigned int enc_f(float f) {
    unsigned int u = __float_as_uint(f);
    return (u & 0x80000000u) ? ~u : (u | 0x80000000u);
}
__device__ __forceinline__ float dec_f(unsigned int u) {
    u = (u & 0x80000000u) ? (u & 0x7FFFFFFFu) : ~u;
    return __uint_as_float(u);
}

// The linspace grid point, matching f32 "lo + j*step" with exact endpoint.
__device__ __forceinline__ float xval(int j, float lo, float hi, float step) {
    return (j >= NX - 1) ? hi : fmaf((float)j, step, lo);
}

// ---------------- kernel 1: global min/max over both arrays -----------------
__global__ void __launch_bounds__(256) minmax_k(const float* __restrict__ a,
                                                const float* __restrict__ b, int n) {
    int n4 = n >> 2;
    const float4* __restrict__ a4 = (const float4*)a;
    const float4* __restrict__ b4 = (const float4*)b;
    float mn = CUDART_INF_F, mx = -CUDART_INF_F;
    int S = gridDim.x * blockDim.x;
    int i = blockIdx.x * blockDim.x + threadIdx.x;
    // 2-way unroll: 4 independent LDG.128 in flight per iteration
    for (; i + S < n4; i += 2 * S) {
        float4 v0 = a4[i];
        float4 v1 = a4[i + S];
        float4 w0 = b4[i];
        float4 w1 = b4[i + S];
        mn = fminf(mn, fminf(fminf(v0.x, v0.y), fminf(v0.z, v0.w)));
        mx = fmaxf(mx, fmaxf(fmaxf(v0.x, v0.y), fmaxf(v0.z, v0.w)));
        mn = fminf(mn, fminf(fminf(v1.x, v1.y), fminf(v1.z, v1.w)));
        mx = fmaxf(mx, fmaxf(fmaxf(v1.x, v1.y), fmaxf(v1.z, v1.w)));
        mn = fminf(mn, fminf(fminf(w0.x, w0.y), fminf(w0.z, w0.w)));
        mx = fmaxf(mx, fmaxf(fmaxf(w0.x, w0.y), fmaxf(w0.z, w0.w)));
        mn = fminf(mn, fminf(fminf(w1.x, w1.y), fminf(w1.z, w1.w)));
        mx = fmaxf(mx, fmaxf(fmaxf(w1.x, w1.y), fmaxf(w1.z, w1.w)));
    }
    for (; i < n4; i += S) {
        float4 v0 = a4[i];
        float4 w0 = b4[i];
        mn = fminf(mn, fminf(fminf(v0.x, v0.y), fminf(v0.z, v0.w)));
        mx = fmaxf(mx, fmaxf(fmaxf(v0.x, v0.y), fmaxf(v0.z, v0.w)));
        mn = fminf(mn, fminf(fminf(w0.x, w0.y), fminf(w0.z, w0.w)));
        mx = fmaxf(mx, fmaxf(fmaxf(w0.x, w0.y), fmaxf(w0.z, w0.w)));
    }
    if (blockIdx.x == 0 && threadIdx.x == 0) {   // scalar tail (n % 4)
        for (int k = (n4 << 2); k < n; ++k) {
            mn = fminf(mn, fminf(a[k], b[k]));
            mx = fmaxf(mx, fmaxf(a[k], b[k]));
        }
    }
    for (int o = 16; o; o >>= 1) {
        mn = fminf(mn, __shfl_xor_sync(0xFFFFFFFFu, mn, o));
        mx = fmaxf(mx, __shfl_xor_sync(0xFFFFFFFFu, mx, o));
    }
    __shared__ float smn[32], smx[32];
    int lane = threadIdx.x & 31, w = threadIdx.x >> 5;
    if (lane == 0) { smn[w] = mn; smx[w] = mx; }
    __syncthreads();
    if (threadIdx.x < 32) {
        int nw = blockDim.x >> 5;
        mn = (threadIdx.x < nw) ? smn[threadIdx.x] : CUDART_INF_F;
        mx = (threadIdx.x < nw) ? smx[threadIdx.x] : -CUDART_INF_F;
        for (int o = 16; o; o >>= 1) {
            mn = fminf(mn, __shfl_xor_sync(0xFFFFFFFFu, mn, o));
            mx = fmaxf(mx, __shfl_xor_sync(0xFFFFFFFFu, mx, o));
        }
        if (threadIdx.x == 0) {
            atomicMax(&g_negmin_bits, ~enc_f(mn));
            atomicMax(&g_max_bits, enc_f(mx));
        }
    }
}

// first grid index j with x_j >= v.
// ceil((v-lo)*invstep) is provably within +/-1 of the answer, so ONE
// predicated step each way suffices (short dependency chain, no branches).
__device__ __forceinline__ int binof(float v, float lo, float hi,
                                     float step, float invstep) {
    float f = (v - lo) * invstep;          // f >= 0 since v >= lo
    int j = (int)ceilf(f);
    j = min(j, NX - 1);
    j += (j < NX - 1 && xval(j, lo, hi, step) < v) ? 1 : 0;
    j -= (j > 0 && xval(j - 1, lo, hi, step) >= v) ? 1 : 0;
    return j;
}

__device__ __forceinline__ void hist8(float4 v, float4 w,
                                      unsigned int* h0, unsigned int* h1,
                                      float lo, float hi, float step, float invstep) {
    atomicAdd(&h0[binof(v.x, lo, hi, step, invstep)], 1u);
    atomicAdd(&h0[binof(v.y, lo, hi, step, invstep)], 1u);
    atomicAdd(&h0[binof(v.z, lo, hi, step, invstep)], 1u);
    atomicAdd(&h0[binof(v.w, lo, hi, step, invstep)], 1u);
    atomicAdd(&h1[binof(w.x, lo, hi, step, invstep)], 1u);
    atomicAdd(&h1[binof(w.y, lo, hi, step, invstep)], 1u);
    atomicAdd(&h1[binof(w.z, lo, hi, step, invstep)], 1u);
    atomicAdd(&h1[binof(w.w, lo, hi, step, invstep)], 1u);
}

// ---------------- kernel 2: 2x 1000-bin histograms --------------------------
// Iterates in REVERSE order so the first data it touches is what minmax_k
// read last -> still resident in the 126MB L2 -> less DRAM re-read traffic.
__global__ void __launch_bounds__(256) hist_k(const float* __restrict__ a,
                                              const float* __restrict__ b, int n) {
    __shared__ unsigned int sh[2][NX];
    for (int i = threadIdx.x; i < 2 * NX; i += blockDim.x)
        ((unsigned int*)sh)[i] = 0u;
    __syncthreads();

    float lo = dec_f(~g_negmin_bits);
    float hi = dec_f(g_max_bits);
    float step = (hi - lo) / (float)(NX - 1);
    float invstep = (step > 0.0f) ? (1.0f / step) : 0.0f;

    int n4 = n >> 2;
    const float4* __restrict__ a4 = (const float4*)a;
    const float4* __restrict__ b4 = (const float4*)b;
    int S = gridDim.x * blockDim.x;
    int i = blockIdx.x * blockDim.x + threadIdx.x;
    int last = n4 - 1;
    for (; i + S < n4; i += 2 * S) {
        int i0 = last - i;
        int i1 = last - (i + S);
        float4 v0 = a4[i0];
        float4 v1 = a4[i1];
        float4 w0 = b4[i0];
        float4 w1 = b4[i1];
        hist8(v0, w0, sh[0], sh[1], lo, hi, step, invstep);
        hist8(v1, w1, sh[0], sh[1], lo, hi, step, invstep);
    }
    for (; i < n4; i += S) {
        int i0 = last - i;
        float4 v0 = a4[i0];
        float4 w0 = b4[i0];
        hist8(v0, w0, sh[0], sh[1], lo, hi, step, invstep);
    }
    if (blockIdx.x == 0 && threadIdx.x == 0) {   // scalar tail
        for (int k = (n4 << 2); k < n; ++k) {
            atomicAdd(&sh[0][binof(a[k], lo, hi, step, invstep)], 1u);
            atomicAdd(&sh[1][binof(b[k], lo, hi, step, invstep)], 1u);
        }
    }
    __syncthreads();
    for (int i2 = threadIdx.x; i2 < NX; i2 += blockDim.x) {
        unsigned int c0 = sh[0][i2];
        unsigned int c1 = sh[1][i2];
        if (c0) atomicAdd(&g_hist[0][i2], c0);
        if (c1) atomicAdd(&g_hist[1][i2], c1);
    }
}

// ---------------- kernel 3: scan + trapz + STATE RESET (single block) -------
__global__ void finish_k(float* __restrict__ out, int n) {
    int t = threadIdx.x;
    int lane = t & 31, w = t >> 5;

    float lo = dec_f(~g_negmin_bits);
    float hi = dec_f(g_max_bits);
    float step = (hi - lo) / (float)(NX - 1);

    unsigned int s0 = (t < NX) ? g_hist[0][t] : 0u;
    unsigned int s1 = (t < NX) ? g_hist[1][t] : 0u;

    #pragma unroll
    for (int o = 1; o < 32; o <<= 1) {
        unsigned int u0 = __shfl_up_sync(0xFFFFFFFFu, s0, o);
        unsigned int u1 = __shfl_up_sync(0xFFFFFFFFu, s1, o);
        if (lane >= o) { s0 += u0; s1 += u1; }
    }
    __shared__ unsigned int ws0[32], ws1[32];
    if (lane == 31) { ws0[w] = s0; ws1[w] = s1; }
    __syncthreads();
    if (w == 0) {
        unsigned int a0 = ws0[lane], a1 = ws1[lane];
        #pragma unroll
        for (int o = 1; o < 32; o <<= 1) {
            unsigned int u0 = __shfl_up_sync(0xFFFFFFFFu, a0, o);
            unsigned int u1 = __shfl_up_sync(0xFFFFFFFFu, a1, o);
            if (lane >= o) { a0 += u0; a1 += u1; }
        }
        ws0[lane] = a0; ws1[lane] = a1;
    }
    __syncthreads();
    if (w > 0) { s0 += ws0[w - 1]; s1 += ws1[w - 1]; }

    __shared__ unsigned int sc0[1024], sc1[1024];
    sc0[t] = s0; sc1[t] = s1;
    __syncthreads();

    float nf = (float)n;
    double acc = 0.0;
    if (t < NX - 1) {
        float cp0 = (float)sc0[t] / nf;
        float ct0 = (float)sc1[t] / nf;
        float cp1 = (float)sc0[t + 1] / nf;
        float ct1 = (float)sc1[t + 1] / nf;
        float y0 = cp0 - ct0; y0 = y0 * y0;
        float y1 = cp1 - ct1; y1 = y1 * y1;
        float dx = xval(t + 1, lo, hi, step) - xval(t, lo, hi, step);
        acc = (double)(0.5f * (y0 + y1) * dx);
    }
    for (int o = 16; o; o >>= 1)
        acc += __shfl_xor_sync(0xFFFFFFFFu, acc, o);
    __shared__ double sd[32];
    if (lane == 0) sd[w] = acc;
    __syncthreads();
    if (t < 32) {
        acc = sd[t];
        for (int o = 16; o; o >>= 1)
            acc += __shfl_xor_sync(0xFFFFFFFFu, acc, o);
        if (t == 0) out[0] = (float)acc;
    }

    // ---- reset all device state for the next graph replay ----
    __syncthreads();
    for (int i = t; i < 2 * NX; i += 1024)
        ((unsigned int*)g_hist)[i] = 0u;
    if (t == 0) { g_negmin_bits = 0u; g_max_bits = 0u; }
}

// ---------------- launch ----------------------------------------------------
extern "C" void kernel_launch(void* const* d_in, const int* in_sizes, int n_in,
                              void* d_out, int out_size) {
    const float* p = (const float*)d_in[0];
    const float* tg = (const float*)d_in[1];
    int n = in_sizes[0];

    minmax_k<<<1184, 256>>>(p, tg, n);
    hist_k<<<1184, 256>>>(p, tg, n);
    finish_k<<<1, 1024>>>((float*)d_out, n);
}

// round 6
// speedup vs baseline: 2.6265x; 1.3011x over previous
#include <cuda_runtime.h>
#include <math_constants.h>

#define NX 1000

// ---------------- device-global scratch (zero-init is the neutral state) ----
__device__ unsigned int g_negmin_bits;   // holds max(~enc(v))  -> min value
__device__ unsigned int g_max_bits;      // holds max( enc(v))  -> max value
__device__ unsigned int g_hist[2][NX];
__device__ unsigned int g_ticket;        // last-block detection

__device__ __forceinline__ unsigned int enc_f(float f) {
    unsigned int u = __float_as_uint(f);
    return (u & 0x80000000u) ? ~u : (u | 0x80000000u);
}
__device__ __forceinline__ float dec_f(unsigned int u) {
    u = (u & 0x80000000u) ? (u & 0x7FFFFFFFu) : ~u;
    return __uint_as_float(u);
}

// The linspace grid point, matching f32 "lo + j*step" with exact endpoint.
__device__ __forceinline__ float xval(int j, float lo, float hi, float step) {
    return (j >= NX - 1) ? hi : fmaf((float)j, step, lo);
}

// ---------------- kernel 1: global min/max over both arrays -----------------
__global__ void __launch_bounds__(256) minmax_k(const float* __restrict__ a,
                                                const float* __restrict__ b, int n) {
    int n4 = n >> 2;
    const float4* __restrict__ a4 = (const float4*)a;
    const float4* __restrict__ b4 = (const float4*)b;
    float mn = CUDART_INF_F, mx = -CUDART_INF_F;
    int S = gridDim.x * blockDim.x;
    int i = blockIdx.x * blockDim.x + threadIdx.x;
    for (; i + S < n4; i += 2 * S) {
        float4 v0 = a4[i];
        float4 v1 = a4[i + S];
        float4 w0 = b4[i];
        float4 w1 = b4[i + S];
        mn = fminf(mn, fminf(fminf(v0.x, v0.y), fminf(v0.z, v0.w)));
        mx = fmaxf(mx, fmaxf(fmaxf(v0.x, v0.y), fmaxf(v0.z, v0.w)));
        mn = fminf(mn, fminf(fminf(v1.x, v1.y), fminf(v1.z, v1.w)));
        mx = fmaxf(mx, fmaxf(fmaxf(v1.x, v1.y), fmaxf(v1.z, v1.w)));
        mn = fminf(mn, fminf(fminf(w0.x, w0.y), fminf(w0.z, w0.w)));
        mx = fmaxf(mx, fmaxf(fmaxf(w0.x, w0.y), fmaxf(w0.z, w0.w)));
        mn = fminf(mn, fminf(fminf(w1.x, w1.y), fminf(w1.z, w1.w)));
        mx = fmaxf(mx, fmaxf(fmaxf(w1.x, w1.y), fmaxf(w1.z, w1.w)));
    }
    for (; i < n4; i += S) {
        float4 v0 = a4[i];
        float4 w0 = b4[i];
        mn = fminf(mn, fminf(fminf(v0.x, v0.y), fminf(v0.z, v0.w)));
        mx = fmaxf(mx, fmaxf(fmaxf(v0.x, v0.y), fmaxf(v0.z, v0.w)));
        mn = fminf(mn, fminf(fminf(w0.x, w0.y), fminf(w0.z, w0.w)));
        mx = fmaxf(mx, fmaxf(fmaxf(w0.x, w0.y), fmaxf(w0.z, w0.w)));
    }
    if (blockIdx.x == 0 && threadIdx.x == 0) {   // scalar tail (n % 4)
        for (int k = (n4 << 2); k < n; ++k) {
            mn = fminf(mn, fminf(a[k], b[k]));
            mx = fmaxf(mx, fmaxf(a[k], b[k]));
        }
    }
    for (int o = 16; o; o >>= 1) {
        mn = fminf(mn, __shfl_xor_sync(0xFFFFFFFFu, mn, o));
        mx = fmaxf(mx, __shfl_xor_sync(0xFFFFFFFFu, mx, o));
    }
    __shared__ float smn[32], smx[32];
    int lane = threadIdx.x & 31, w = threadIdx.x >> 5;
    if (lane == 0) { smn[w] = mn; smx[w] = mx; }
    __syncthreads();
    if (threadIdx.x < 32) {
        int nw = blockDim.x >> 5;
        mn = (threadIdx.x < nw) ? smn[threadIdx.x] : CUDART_INF_F;
        mx = (threadIdx.x < nw) ? smx[threadIdx.x] : -CUDART_INF_F;
        for (int o = 16; o; o >>= 1) {
            mn = fminf(mn, __shfl_xor_sync(0xFFFFFFFFu, mn, o));
            mx = fmaxf(mx, __shfl_xor_sync(0xFFFFFFFFu, mx, o));
        }
        if (threadIdx.x == 0) {
            atomicMax(&g_negmin_bits, ~enc_f(mn));
            atomicMax(&g_max_bits, enc_f(mx));
        }
    }
}

// Cheap bin: ceil((v-lo)/step) clamped. Boundary tie-breaks (sub-ulp) are
// dropped: ~16K of 33.2M elements may shift by one bin; integral effect <<1e-3.
__device__ __forceinline__ int binof(float v, float invstep, float negloinv) {
    float f = fmaf(v, invstep, negloinv);    // (v - lo) / step
    int j = (int)ceilf(f);                   // f >= -eps, ceil >= 0
    return min(j, NX - 1);
}

__device__ __forceinline__ void hist8(float4 v, float4 w,
                                      unsigned int* h0, unsigned int* h1,
                                      float invstep, float negloinv) {
    atomicAdd(&h0[binof(v.x, invstep, negloinv)], 1u);
    atomicAdd(&h0[binof(v.y, invstep, negloinv)], 1u);
    atomicAdd(&h0[binof(v.z, invstep, negloinv)], 1u);
    atomicAdd(&h0[binof(v.w, invstep, negloinv)], 1u);
    atomicAdd(&h1[binof(w.x, invstep, negloinv)], 1u);
    atomicAdd(&h1[binof(w.y, invstep, negloinv)], 1u);
    atomicAdd(&h1[binof(w.z, invstep, negloinv)], 1u);
    atomicAdd(&h1[binof(w.w, invstep, negloinv)], 1u);
}

// ------- kernel 2: histograms + (last block) scan + trapz + state reset -----
__global__ void __launch_bounds__(256) hist_finish_k(const float* __restrict__ a,
                                                     const float* __restrict__ b,
                                                     int n, float* __restrict__ out) {
    __shared__ unsigned int sh0[NX];
    __shared__ unsigned int sh1[NX];
    int t = threadIdx.x;
    for (int i = t; i < NX; i += blockDim.x) { sh0[i] = 0u; sh1[i] = 0u; }
    __syncthreads();

    float lo = dec_f(~g_negmin_bits);
    float hi = dec_f(g_max_bits);
    float step = (hi - lo) / (float)(NX - 1);
    float invstep = (step > 0.0f) ? (1.0f / step) : 0.0f;
    float negloinv = -lo * invstep;

    int n4 = n >> 2;
    const float4* __restrict__ a4 = (const float4*)a;
    const float4* __restrict__ b4 = (const float4*)b;
    int S = gridDim.x * blockDim.x;
    int i = blockIdx.x * blockDim.x + t;
    int last = n4 - 1;
    // reverse order: first touch what minmax_k read last (still in 126MB L2)
    for (; i + S < n4; i += 2 * S) {
        int i0 = last - i;
        int i1 = last - (i + S);
        float4 v0 = a4[i0];
        float4 v1 = a4[i1];
        float4 w0 = b4[i0];
        float4 w1 = b4[i1];
        hist8(v0, w0, sh0, sh1, invstep, negloinv);
        hist8(v1, w1, sh0, sh1, invstep, negloinv);
    }
    for (; i < n4; i += S) {
        int i0 = last - i;
        float4 v0 = a4[i0];
        float4 w0 = b4[i0];
        hist8(v0, w0, sh0, sh1, invstep, negloinv);
    }
    if (blockIdx.x == 0 && t == 0) {   // scalar tail
        for (int k = (n4 << 2); k < n; ++k) {
            atomicAdd(&sh0[binof(a[k], invstep, negloinv)], 1u);
            atomicAdd(&sh1[binof(b[k], invstep, negloinv)], 1u);
        }
    }
    __syncthreads();
    for (int i2 = t; i2 < NX; i2 += blockDim.x) {
        unsigned int c0 = sh0[i2];
        unsigned int c1 = sh1[i2];
        if (c0) atomicAdd(&g_hist[0][i2], c0);
        if (c1) atomicAdd(&g_hist[1][i2], c1);
    }
    __syncthreads();

    // ---- last-arriving block runs the finish phase (no spin, no deadlock) ----
    __shared__ unsigned int s_last;
    if (t == 0) {
        __threadfence();
        s_last = (atomicAdd(&g_ticket, 1u) == gridDim.x - 1u) ? 1u : 0u;
    }
    __syncthreads();
    if (!s_last) return;
    __threadfence();

    int lane = t & 31, w = t >> 5;
    // each of 256 threads owns 4 bins
    unsigned int c0[4], c1[4];
    int base = 4 * t;
    #pragma unroll
    for (int k = 0; k < 4; ++k) {
        int idx = base + k;
        c0[k] = (idx < NX) ? __ldcg(&g_hist[0][idx]) : 0u;
        c1[k] = (idx < NX) ? __ldcg(&g_hist[1][idx]) : 0u;
    }
    // thread-local inclusive
    c0[1] += c0[0]; c0[2] += c0[1]; c0[3] += c0[2];
    c1[1] += c1[0]; c1[2] += c1[1]; c1[3] += c1[2];
    unsigned int tc = c0[3], td = c1[3];
    unsigned int ic = tc, id = td;
    #pragma unroll
    for (int o = 1; o < 32; o <<= 1) {
        unsigned int u0 = __shfl_up_sync(0xFFFFFFFFu, ic, o);
        unsigned int u1 = __shfl_up_sync(0xFFFFFFFFu, id, o);
        if (lane >= o) { ic += u0; id += u1; }
    }
    unsigned int exc = ic - tc, exd = id - td;   // exclusive within warp
    __shared__ unsigned int ws0[8], ws1[8];
    if (lane == 31) { ws0[w] = ic; ws1[w] = id; }
    __syncthreads();
    if (w == 0) {
        unsigned int v0 = (lane < 8) ? ws0[lane] : 0u;
        unsigned int v1 = (lane < 8) ? ws1[lane] : 0u;
        #pragma unroll
        for (int o = 1; o < 8; o <<= 1) {
            unsigned int u0 = __shfl_up_sync(0xFFFFFFFFu, v0, o);
            unsigned int u1 = __shfl_up_sync(0xFFFFFFFFu, v1, o);
            if (lane >= o) { v0 += u0; v1 += u1; }
        }
        if (lane < 8) { ws0[lane] = v0; ws1[lane] = v1; }
    }
    __syncthreads();
    unsigned int wb0 = w ? ws0[w - 1] : 0u;
    unsigned int wb1 = w ? ws1[w - 1] : 0u;
    exc += wb0; exd += wb1;
    #pragma unroll
    for (int k = 0; k < 4; ++k) {
        int idx = base + k;
        if (idx < NX) { sh0[idx] = exc + c0[k]; sh1[idx] = exd + c1[k]; }
    }
    __syncthreads();

    // trapz over 999 intervals, f32 term rounding matches reference
    float nf = (float)n;
    double acc = 0.0;
    for (int j = t; j < NX - 1; j += 256) {
        float cp0 = (float)sh0[j] / nf;
        float ct0 = (float)sh1[j] / nf;
        float cp1 = (float)sh0[j + 1] / nf;
        float ct1 = (float)sh1[j + 1] / nf;
        float y0 = cp0 - ct0; y0 = y0 * y0;
        float y1 = cp1 - ct1; y1 = y1 * y1;
        float dx = xval(j + 1, lo, hi, step) - xval(j, lo, hi, step);
        acc += (double)(0.5f * (y0 + y1) * dx);
    }
    for (int o = 16; o; o >>= 1)
        acc += __shfl_xor_sync(0xFFFFFFFFu, acc, o);
    __shared__ double sd[8];
    if (lane == 0) sd[w] = acc;
    __syncthreads();
    if (t == 0) {
        double s = 0.0;
        #pragma unroll
        for (int q = 0; q < 8; ++q) s += sd[q];
        out[0] = (float)s;
    }

    // ---- reset all device state for the next graph replay ----
    __syncthreads();
    for (int i3 = t; i3 < 2 * NX; i3 += 256)
        ((unsigned int*)g_hist)[i3] = 0u;
    if (t == 0) { g_negmin_bits = 0u; g_max_bits = 0u; g_ticket = 0u; }
}

// ---------------- launch ----------------------------------------------------
extern "C" void kernel_launch(void* const* d_in, const int* in_sizes, int n_in,
                              void* d_out, int out_size) {
    const float* p = (const float*)d_in[0];
    const float* tg = (const float*)d_in[1];
    int n = in_sizes[0];

    minmax_k<<<1184, 256>>>(p, tg, n);
    hist_finish_k<<<592, 256>>>(p, tg, n, (float*)d_out);
}

// round 7
// speedup vs baseline: 2.6941x; 1.0257x over previous
#include <cuda_runtime.h>
#include <math_constants.h>

#define NX 1000
#define HB 592          // hist grid
#define HT 512          // hist block (4 CTAs/SM -> 100% occ)

// ---------------- device-global scratch (zero-init is the neutral state) ----
__device__ unsigned int g_negmin_bits;   // holds max(~enc(v))  -> min value
__device__ unsigned int g_max_bits;      // holds max( enc(v))  -> max value
__device__ unsigned int g_hist[2][NX];
__device__ unsigned int g_ticket;        // last-block detection

__device__ __forceinline__ unsigned int enc_f(float f) {
    unsigned int u = __float_as_uint(f);
    return (u & 0x80000000u) ? ~u : (u | 0x80000000u);
}
__device__ __forceinline__ float dec_f(unsigned int u) {
    u = (u & 0x80000000u) ? (u & 0x7FFFFFFFu) : ~u;
    return __uint_as_float(u);
}

// The linspace grid point, matching f32 "lo + j*step" with exact endpoint.
__device__ __forceinline__ float xval(int j, float lo, float hi, float step) {
    return (j >= NX - 1) ? hi : fmaf((float)j, step, lo);
}

// ---------------- kernel 1: global min/max over both arrays -----------------
__global__ void __launch_bounds__(256) minmax_k(const float* __restrict__ a,
                                                const float* __restrict__ b, int n) {
    int n4 = n >> 2;
    const float4* __restrict__ a4 = (const float4*)a;
    const float4* __restrict__ b4 = (const float4*)b;
    float mn = CUDART_INF_F, mx = -CUDART_INF_F;
    int S = gridDim.x * blockDim.x;
    int i = blockIdx.x * blockDim.x + threadIdx.x;
    for (; i + S < n4; i += 2 * S) {
        float4 v0 = a4[i];
        float4 v1 = a4[i + S];
        float4 w0 = b4[i];
        float4 w1 = b4[i + S];
        mn = fminf(mn, fminf(fminf(v0.x, v0.y), fminf(v0.z, v0.w)));
        mx = fmaxf(mx, fmaxf(fmaxf(v0.x, v0.y), fmaxf(v0.z, v0.w)));
        mn = fminf(mn, fminf(fminf(v1.x, v1.y), fminf(v1.z, v1.w)));
        mx = fmaxf(mx, fmaxf(fmaxf(v1.x, v1.y), fmaxf(v1.z, v1.w)));
        mn = fminf(mn, fminf(fminf(w0.x, w0.y), fminf(w0.z, w0.w)));
        mx = fmaxf(mx, fmaxf(fmaxf(w0.x, w0.y), fmaxf(w0.z, w0.w)));
        mn = fminf(mn, fminf(fminf(w1.x, w1.y), fminf(w1.z, w1.w)));
        mx = fmaxf(mx, fmaxf(fmaxf(w1.x, w1.y), fmaxf(w1.z, w1.w)));
    }
    for (; i < n4; i += S) {
        float4 v0 = a4[i];
        float4 w0 = b4[i];
        mn = fminf(mn, fminf(fminf(v0.x, v0.y), fminf(v0.z, v0.w)));
        mx = fmaxf(mx, fmaxf(fmaxf(v0.x, v0.y), fmaxf(v0.z, v0.w)));
        mn = fminf(mn, fminf(fminf(w0.x, w0.y), fminf(w0.z, w0.w)));
        mx = fmaxf(mx, fmaxf(fmaxf(w0.x, w0.y), fmaxf(w0.z, w0.w)));
    }
    if (blockIdx.x == 0 && threadIdx.x == 0) {   // scalar tail (n % 4)
        for (int k = (n4 << 2); k < n; ++k) {
            mn = fminf(mn, fminf(a[k], b[k]));
            mx = fmaxf(mx, fmaxf(a[k], b[k]));
        }
    }
    for (int o = 16; o; o >>= 1) {
        mn = fminf(mn, __shfl_xor_sync(0xFFFFFFFFu, mn, o));
        mx = fmaxf(mx, __shfl_xor_sync(0xFFFFFFFFu, mx, o));
    }
    __shared__ float smn[32], smx[32];
    int lane = threadIdx.x & 31, w = threadIdx.x >> 5;
    if (lane == 0) { smn[w] = mn; smx[w] = mx; }
    __syncthreads();
    if (threadIdx.x < 32) {
        int nw = blockDim.x >> 5;
        mn = (threadIdx.x < nw) ? smn[threadIdx.x] : CUDART_INF_F;
        mx = (threadIdx.x < nw) ? smx[threadIdx.x] : -CUDART_INF_F;
        for (int o = 16; o; o >>= 1) {
            mn = fminf(mn, __shfl_xor_sync(0xFFFFFFFFu, mn, o));
            mx = fmaxf(mx, __shfl_xor_sync(0xFFFFFFFFu, mx, o));
        }
        if (threadIdx.x == 0) {
            atomicMax(&g_negmin_bits, ~enc_f(mn));
            atomicMax(&g_max_bits, enc_f(mx));
        }
    }
}

// Cheap bin: ceil((v-lo)/step) clamped. Boundary tie-breaks (sub-ulp) are
// dropped: ~16K of 33.2M elements may shift by one bin; integral effect <<1e-3.
__device__ __forceinline__ int binof(float v, float invstep, float negloinv) {
    float f = fmaf(v, invstep, negloinv);    // (v - lo) / step
    int j = (int)ceilf(f);                   // f >= -eps, ceil >= 0
    return min(j, NX - 1);
}

__device__ __forceinline__ void hist8(float4 v, float4 w,
                                      unsigned int* h0, unsigned int* h1,
                                      float invstep, float negloinv) {
    atomicAdd(&h0[binof(v.x, invstep, negloinv)], 1u);
    atomicAdd(&h0[binof(v.y, invstep, negloinv)], 1u);
    atomicAdd(&h0[binof(v.z, invstep, negloinv)], 1u);
    atomicAdd(&h0[binof(v.w, invstep, negloinv)], 1u);
    atomicAdd(&h1[binof(w.x, invstep, negloinv)], 1u);
    atomicAdd(&h1[binof(w.y, invstep, negloinv)], 1u);
    atomicAdd(&h1[binof(w.z, invstep, negloinv)], 1u);
    atomicAdd(&h1[binof(w.w, invstep, negloinv)], 1u);
}

// ------- kernel 2: histograms + (last block) scan + trapz + state reset -----
__global__ void __launch_bounds__(HT) hist_finish_k(const float* __restrict__ a,
                                                    const float* __restrict__ b,
                                                    int n, float* __restrict__ out) {
    __shared__ unsigned int sh0[NX];
    __shared__ unsigned int sh1[NX];
    int t = threadIdx.x;
    for (int i = t; i < NX; i += HT) { sh0[i] = 0u; sh1[i] = 0u; }
    __syncthreads();

    float lo = dec_f(~g_negmin_bits);
    float hi = dec_f(g_max_bits);
    float step = (hi - lo) / (float)(NX - 1);
    float invstep = (step > 0.0f) ? (1.0f / step) : 0.0f;
    float negloinv = -lo * invstep;

    int n4 = n >> 2;
    const float4* __restrict__ a4 = (const float4*)a;
    const float4* __restrict__ b4 = (const float4*)b;
    int S = gridDim.x * HT;
    int i = blockIdx.x * HT + t;
    int last = n4 - 1;
    // reverse order: first touch what minmax_k read last (still in 126MB L2)
    for (; i + S < n4; i += 2 * S) {
        int i0 = last - i;
        int i1 = last - (i + S);
        float4 v0 = a4[i0];
        float4 v1 = a4[i1];
        float4 w0 = b4[i0];
        float4 w1 = b4[i1];
        hist8(v0, w0, sh0, sh1, invstep, negloinv);
        hist8(v1, w1, sh0, sh1, invstep, negloinv);
    }
    for (; i < n4; i += S) {
        int i0 = last - i;
        float4 v0 = a4[i0];
        float4 w0 = b4[i0];
        hist8(v0, w0, sh0, sh1, invstep, negloinv);
    }
    if (blockIdx.x == 0 && t == 0) {   // scalar tail
        for (int k = (n4 << 2); k < n; ++k) {
            atomicAdd(&sh0[binof(a[k], invstep, negloinv)], 1u);
            atomicAdd(&sh1[binof(b[k], invstep, negloinv)], 1u);
        }
    }
    __syncthreads();
    for (int i2 = t; i2 < NX; i2 += HT) {
        unsigned int c0 = sh0[i2];
        unsigned int c1 = sh1[i2];
        if (c0) atomicAdd(&g_hist[0][i2], c0);
        if (c1) atomicAdd(&g_hist[1][i2], c1);
    }
    __syncthreads();

    // ---- last-arriving block runs the finish phase (no spin, no deadlock) ----
    __shared__ unsigned int s_last;
    if (t == 0) {
        __threadfence();
        s_last = (atomicAdd(&g_ticket, 1u) == gridDim.x - 1u) ? 1u : 0u;
    }
    __syncthreads();
    if (!s_last) return;
    __threadfence();

    int lane = t & 31, w = t >> 5;   // 16 warps
    // each of 512 threads owns 2 bins
    unsigned int c0[2], c1[2];
    int base = 2 * t;
    #pragma unroll
    for (int k = 0; k < 2; ++k) {
        int idx = base + k;
        c0[k] = (idx < NX) ? __ldcg(&g_hist[0][idx]) : 0u;
        c1[k] = (idx < NX) ? __ldcg(&g_hist[1][idx]) : 0u;
    }
    c0[1] += c0[0];
    c1[1] += c1[0];
    unsigned int tc = c0[1], td = c1[1];
    unsigned int ic = tc, id = td;
    #pragma unroll
    for (int o = 1; o < 32; o <<= 1) {
        unsigned int u0 = __shfl_up_sync(0xFFFFFFFFu, ic, o);
        unsigned int u1 = __shfl_up_sync(0xFFFFFFFFu, id, o);
        if (lane >= o) { ic += u0; id += u1; }
    }
    unsigned int exc = ic - tc, exd = id - td;   // exclusive within warp
    __shared__ unsigned int ws0[16], ws1[16];
    if (lane == 31) { ws0[w] = ic; ws1[w] = id; }
    __syncthreads();
    if (w == 0) {
        unsigned int v0 = (lane < 16) ? ws0[lane] : 0u;
        unsigned int v1 = (lane < 16) ? ws1[lane] : 0u;
        #pragma unroll
        for (int o = 1; o < 16; o <<= 1) {
            unsigned int u0 = __shfl_up_sync(0xFFFFFFFFu, v0, o);
            unsigned int u1 = __shfl_up_sync(0xFFFFFFFFu, v1, o);
            if (lane >= o) { v0 += u0; v1 += u1; }
        }
        if (lane < 16) { ws0[lane] = v0; ws1[lane] = v1; }
    }
    __syncthreads();
    unsigned int wb0 = w ? ws0[w - 1] : 0u;
    unsigned int wb1 = w ? ws1[w - 1] : 0u;
    exc += wb0; exd += wb1;
    #pragma unroll
    for (int k = 0; k < 2; ++k) {
        int idx = base + k;
        if (idx < NX) { sh0[idx] = exc + c0[k]; sh1[idx] = exd + c1[k]; }
    }
    __syncthreads();

    // trapz over 999 intervals, f32 term rounding matches reference
    float nf = (float)n;
    double acc = 0.0;
    for (int j = t; j < NX - 1; j += HT) {
        float cp0 = (float)sh0[j] / nf;
        float ct0 = (float)sh1[j] / nf;
        float cp1 = (float)sh0[j + 1] / nf;
        float ct1 = (float)sh1[j + 1] / nf;
        float y0 = cp0 - ct0; y0 = y0 * y0;
        float y1 = cp1 - ct1; y1 = y1 * y1;
        float dx = xval(j + 1, lo, hi, step) - xval(j, lo, hi, step);
        acc += (double)(0.5f * (y0 + y1) * dx);
    }
    for (int o = 16; o; o >>= 1)
        acc += __shfl_xor_sync(0xFFFFFFFFu, acc, o);
    __shared__ double sd[16];
    if (lane == 0) sd[w] = acc;
    __syncthreads();
    if (t == 0) {
        double s = 0.0;
        #pragma unroll
        for (int q = 0; q < 16; ++q) s += sd[q];
        out[0] = (float)s;
    }

    // ---- reset all device state for the next graph replay ----
    __syncthreads();
    for (int i3 = t; i3 < 2 * NX; i3 += HT)
        ((unsigned int*)g_hist)[i3] = 0u;
    if (t == 0) { g_negmin_bits = 0u; g_max_bits = 0u; g_ticket = 0u; }
}

// ---------------- launch ----------------------------------------------------
extern "C" void kernel_launch(void* const* d_in, const int* in_sizes, int n_in,
                              void* d_out, int out_size) {
    const float* p = (const float*)d_in[0];
    const float* tg = (const float*)d_in[1];
    int n = in_sizes[0];

    minmax_k<<<1184, 256>>>(p, tg, n);
    hist_finish_k<<<HB, HT>>>(p, tg, n, (float*)d_out);
}